// round 12
// baseline (speedup 1.0000x reference)
#include <cuda_runtime.h>
#include <cstdint>
#include <math.h>

// Problem constants: B=1024, H=32, N=25, F=D=128
#define BH      32768
#define NK      26                  // softmax/aggregation length (self + 25)
#define FDIM    128
#define DDIM    128
#define GRIDSZ  304                 // 2 blocks/SM x 152 SMs (GB300)
#define THREADS 256
#define NPAIR   3                   // TMA ring depth in row-pairs
#define NSLOT   (2 * NPAIR)

#define ROW_FLOATS   (NK * FDIM)    // 3328 floats per staged row tile
#define SELF_BYTES   (FDIM * 4)     // 512
#define NEIGH_BYTES  (25 * FDIM * 4)// 12800
#define ROW_BYTES    (SELF_BYTES + NEIGH_BYTES) // 13312

typedef unsigned long long ull;

// ---------------------------------------------------------------------------
// TMA 1D bulk copy + mbarrier helpers
// ---------------------------------------------------------------------------
__device__ __forceinline__ void tma_bulk_1d(unsigned dst, const void* src,
                                            unsigned bytes, unsigned mbar) {
    asm volatile(
        "cp.async.bulk.shared::cluster.global.mbarrier::complete_tx::bytes "
        "[%0], [%1], %2, [%3];\n"
        :: "r"(dst), "l"(src), "r"(bytes), "r"(mbar) : "memory");
}
__device__ __forceinline__ void mbar_init(unsigned mbar, unsigned cnt) {
    asm volatile("mbarrier.init.shared.b64 [%0], %1;\n" :: "r"(mbar), "r"(cnt) : "memory");
}
__device__ __forceinline__ void mbar_expect_tx(unsigned mbar, unsigned bytes) {
    asm volatile("mbarrier.arrive.expect_tx.shared.b64 _, [%0], %1;\n"
                 :: "r"(mbar), "r"(bytes) : "memory");
}
__device__ __forceinline__ void mbar_wait(unsigned mbar, unsigned parity) {
    asm volatile(
        "{\n\t"
        ".reg .pred P;\n\t"
        "WL_%=:\n\t"
        "mbarrier.try_wait.parity.acquire.cta.shared::cta.b64 P, [%0], %1, 0x989680;\n\t"
        "@P bra WD_%=;\n\t"
        "bra WL_%=;\n\t"
        "WD_%=:\n\t"
        "}"
        :: "r"(mbar), "r"(parity) : "memory");
}

// warp all-reduce (shfl butterfly; redux.f32 is NOT supported on sm_103)
__device__ __forceinline__ float warp_redux_add(float v) {
    v += __shfl_xor_sync(0xffffffffu, v, 16);
    v += __shfl_xor_sync(0xffffffffu, v, 8);
    v += __shfl_xor_sync(0xffffffffu, v, 4);
    v += __shfl_xor_sync(0xffffffffu, v, 2);
    v += __shfl_xor_sync(0xffffffffu, v, 1);
    return v;
}
// packed f32x2 dot fragment over a 16-byte chunk: lo+hi of x2a*w2a + x2b*w2b
__device__ __forceinline__ float dot4_f32x2(longlong2 x, ull w_a, ull w_b) {
    ull v;
    asm volatile("mul.rn.f32x2 %0, %1, %2;\n" : "=l"(v) : "l"((ull)x.x), "l"(w_a));
    asm volatile("fma.rn.f32x2 %0, %1, %2, %0;\n" : "+l"(v) : "l"((ull)x.y), "l"(w_b));
    return __uint_as_float((unsigned)v) + __uint_as_float((unsigned)(v >> 32));
}

__global__ void __launch_bounds__(THREADS, 2)
fused_gat_kernel(const float* __restrict__ x_self,
                 const float* __restrict__ x_neigh,
                 const float* __restrict__ W,
                 const float* __restrict__ a_s,
                 const float* __restrict__ a_n,
                 float* __restrict__ out) {
    __shared__ __align__(128) float xs[NSLOT][ROW_FLOATS];      // ~80 KB ring
    __shared__ __align__(16)  float wa_s_sm[FDIM];
    __shared__ __align__(16)  float wa_n_sm[FDIM];
    __shared__ __align__(16)  float xpart[4][4][FDIM];           // per-warp e-weighted partials
    __shared__ float zpart[4][4];                                // per-warp exp sums
    __shared__ __align__(16)  float xagg_il[4][FDIM];            // interleaved for GEMV
    __shared__ __align__(8)   ull  mbars[NPAIR];

    const int t    = threadIdx.x;
    const int warp = t >> 5;
    const int lane = t & 31;

    const unsigned xs_base   = (unsigned)__cvta_generic_to_shared(&xs[0][0]);
    const unsigned mbar_base = (unsigned)__cvta_generic_to_shared(&mbars[0]);

    if (t == 0) {
#pragma unroll
        for (int i = 0; i < NPAIR; i++) mbar_init(mbar_base + 8 * i, 1);
        asm volatile("fence.proxy.async.shared::cta;\n" ::: "memory");
    }
    __syncthreads();

    const int G = GRIDSZ;
    auto issue_pair = [&](int p) {
        int rA = blockIdx.x + 2 * p * G;
        if (rA >= BH) return;
        int rB = rA + G;
        int nrows = (rB < BH) ? 2 : 1;
        unsigned mb = mbar_base + 8 * (p % NPAIR);
        unsigned s0 = xs_base + (unsigned)(2 * (p % NPAIR)) * (ROW_FLOATS * 4);
        mbar_expect_tx(mb, (unsigned)ROW_BYTES * nrows);
        tma_bulk_1d(s0,              x_self  + (size_t)rA * FDIM,      SELF_BYTES,  mb);
        tma_bulk_1d(s0 + SELF_BYTES, x_neigh + (size_t)rA * 25 * FDIM, NEIGH_BYTES, mb);
        if (nrows == 2) {
            unsigned s1 = s0 + ROW_FLOATS * 4;
            tma_bulk_1d(s1,              x_self  + (size_t)rB * FDIM,      SELF_BYTES,  mb);
            tma_bulk_1d(s1 + SELF_BYTES, x_neigh + (size_t)rB * 25 * FDIM, NEIGH_BYTES, mb);
        }
    };
    if (t == 0) { issue_pair(0); issue_pair(1); issue_pair(2); }

    // ---------------- prologue: wa = W @ a  (2 threads per f) ----------------
    {
        const int f  = t >> 1, hf = t & 1;
        const float* wr = W + (size_t)f * DDIM + hf * 64;
        const float* as = a_s + hf * 64;
        const float* an = a_n + hf * 64;
        float vs = 0.f, vn = 0.f;
#pragma unroll
        for (int j = 0; j < 64; j++) {
            float w = wr[j];
            vs = fmaf(w, as[j], vs);
            vn = fmaf(w, an[j], vn);
        }
        vs += __shfl_xor_sync(0xffffffffu, vs, 1);
        vn += __shfl_xor_sync(0xffffffffu, vn, 1);
        if (!hf) { wa_s_sm[f] = vs; wa_n_sm[f] = vn; }
    }

    // W register cache, packed f32x2 along f.
    const int h = lane >> 4;
    const int d = warp * 16 + (lane & 15);
    ull Wreg2[32];
#pragma unroll
    for (int i = 0; i < 32; i++) {
        int f = h * 64 + 2 * i;
        unsigned lo = __float_as_uint(W[(size_t)f * DDIM + d]);
        unsigned hi = __float_as_uint(W[(size_t)(f + 1) * DDIM + d]);
        Wreg2[i] = ((ull)hi << 32) | lo;
    }
    __syncthreads();

    // per-lane wa slices as packed f32x2 pairs (16B per lane)
    longlong2 wanP = reinterpret_cast<const longlong2*>(wa_n_sm)[lane];
    longlong2 wasP = reinterpret_cast<const longlong2*>(wa_s_sm)[lane];

    // ---------------- main loop: 4 rows (2 pairs) per iteration ----------------
    int rowA = blockIdx.x;
    int p = 0;
    const int rsel = warp >> 2;        // row within pair
    const int w4   = warp & 3;

    while (rowA < BH) {
        const bool rv1 = rowA + G     < BH;
        const bool rv2 = rowA + 2 * G < BH;
        const bool rv3 = rowA + 3 * G < BH;

        mbar_wait(mbar_base + 8 * (p % NPAIR), (unsigned)((p / NPAIR) & 1));
        if (rv2)
            mbar_wait(mbar_base + 8 * ((p + 1) % NPAIR),
                      (unsigned)(((p + 1) / NPAIR) & 1));

        const float* slotU = &xs[2 * (p % NPAIR) + rsel][0];
        const float* slotV = &xs[2 * ((p + 1) % NPAIR) + rsel][0];
        const int  u  = rsel,  v = rsel + 2;
        const bool wu = (rsel == 0) || rv1;
        const bool wv = rv2 && ((rsel == 0) || rv3);

        // ---- single-pass online softmax + aggregation, 2 rows interleaved ----
        ull  paU0 = 0, paU1 = 0, paV0 = 0, paV1 = 0;   // packed f32x2 partials
        float zU = 0.f, zV = 0.f;
        longlong2 x0U, x0V;
        float ssU = 0.f, ssV = 0.f;

        if (wu) {
            x0U = reinterpret_cast<const longlong2*>(slotU)[lane];
            ssU = dot4_f32x2(x0U, (ull)wasP.x, (ull)wasP.y);
        }
        if (wv) {
            x0V = reinterpret_cast<const longlong2*>(slotV)[lane];
            ssV = dot4_f32x2(x0V, (ull)wasP.x, (ull)wasP.y);
        }
        ssU = warp_redux_add(ssU);
        ssV = warp_redux_add(ssV);

#pragma unroll
        for (int j = 0; j < 7; j++) {
            const int k = w4 + 4 * j;
            if (k < NK) {
                longlong2 xU, xV;
                float aS = 0.f, bS = 0.f;
                if (wu) {
                    xU = (k == 0) ? x0U
                       : reinterpret_cast<const longlong2*>(slotU + k * FDIM)[lane];
                    aS = dot4_f32x2(xU, (ull)wanP.x, (ull)wanP.y);
                }
                if (wv) {
                    xV = (k == 0) ? x0V
                       : reinterpret_cast<const longlong2*>(slotV + k * FDIM)[lane];
                    bS = dot4_f32x2(xV, (ull)wanP.x, (ull)wanP.y);
                }
                aS = warp_redux_add(aS);
                bS = warp_redux_add(bS);
                if (wu) {
                    float uu = ssU + aS;
                    uu = (uu > 0.f) ? uu : 0.2f * uu;   // LeakyReLU(0.2)
                    float e = __expf(uu);
                    ull e2; asm volatile("mov.b64 %0, {%1, %1};\n" : "=l"(e2) : "f"(e));
                    asm volatile("fma.rn.f32x2 %0, %1, %2, %0;\n"
                                 : "+l"(paU0) : "l"(e2), "l"((ull)xU.x));
                    asm volatile("fma.rn.f32x2 %0, %1, %2, %0;\n"
                                 : "+l"(paU1) : "l"(e2), "l"((ull)xU.y));
                    zU += e;
                }
                if (wv) {
                    float uu = ssV + bS;
                    uu = (uu > 0.f) ? uu : 0.2f * uu;
                    float e = __expf(uu);
                    ull e2; asm volatile("mov.b64 %0, {%1, %1};\n" : "=l"(e2) : "f"(e));
                    asm volatile("fma.rn.f32x2 %0, %1, %2, %0;\n"
                                 : "+l"(paV0) : "l"(e2), "l"((ull)xV.x));
                    asm volatile("fma.rn.f32x2 %0, %1, %2, %0;\n"
                                 : "+l"(paV1) : "l"(e2), "l"((ull)xV.y));
                    zV += e;
                }
            }
        }
        if (wu) {
            longlong2 q; q.x = (long long)paU0; q.y = (long long)paU1;
            reinterpret_cast<longlong2*>(&xpart[u][w4][0])[lane] = q;
            if (lane == 0) zpart[u][w4] = zU;
        }
        if (wv) {
            longlong2 q; q.x = (long long)paV0; q.y = (long long)paV1;
            reinterpret_cast<longlong2*>(&xpart[v][w4][0])[lane] = q;
            if (lane == 0) zpart[v][w4] = zV;
        }
        __syncthreads();               // B3: partials visible; tiles dead

        // refill the two consumed pairs
        if (t == 0) { issue_pair(p + 3); issue_pair(p + 4); }

        // ---- reduce 4 partials, divide by Z -> interleaved xagg ----
        {
            const int r  = t >> 6;     // row 0..3
            const int fp = t & 63;     // f-pair index
            ull q0 = *reinterpret_cast<const ull*>(&xpart[r][0][2 * fp]);
            ull q1 = *reinterpret_cast<const ull*>(&xpart[r][1][2 * fp]);
            ull q2 = *reinterpret_cast<const ull*>(&xpart[r][2][2 * fp]);
            ull q3 = *reinterpret_cast<const ull*>(&xpart[r][3][2 * fp]);
            asm volatile("add.rn.f32x2 %0, %0, %1;\n" : "+l"(q0) : "l"(q1));
            asm volatile("add.rn.f32x2 %0, %0, %1;\n" : "+l"(q2) : "l"(q3));
            asm volatile("add.rn.f32x2 %0, %0, %1;\n" : "+l"(q0) : "l"(q2));
            float rz = __fdividef(1.f, zpart[r][0] + zpart[r][1]
                                     + zpart[r][2] + zpart[r][3]);
            ull rz2;
            asm volatile("mov.b64 %0, {%1, %1};\n" : "=l"(rz2) : "f"(rz));
            asm volatile("mul.rn.f32x2 %0, %0, %1;\n" : "+l"(q0) : "l"(rz2));
            const int sOff = (fp < 32) ? (8 * (fp >> 1) + 2 * (fp & 1))
                                       : (8 * ((fp - 32) >> 1) + 4 + 2 * (fp & 1));
            *reinterpret_cast<ull*>(&xagg_il[r][sOff]) = q0;
        }
        __syncthreads();               // B4: xagg visible

        // ---- GEMV (4 rows) from packed register W; conflict-free LDS.128 ----
#pragma unroll
        for (int r = 0; r < 4; r++) {
            const bool rok = (r == 0) || (r == 1 && rv1) || (r == 2 && rv2) || (r == 3 && rv3);
            if (rok) {
                ull a0 = 0, a1 = 0;
#pragma unroll
                for (int i = 0; i < 16; i++) {
                    longlong2 q = *reinterpret_cast<const longlong2*>(
                        &xagg_il[r][8 * i + 4 * h]);
                    asm volatile("fma.rn.f32x2 %0, %1, %2, %0;\n"
                                 : "+l"(a0) : "l"((ull)q.x), "l"(Wreg2[2 * i]));
                    asm volatile("fma.rn.f32x2 %0, %1, %2, %0;\n"
                                 : "+l"(a1) : "l"((ull)q.y), "l"(Wreg2[2 * i + 1]));
                }
                float o = __uint_as_float((unsigned)a0) +
                          __uint_as_float((unsigned)(a0 >> 32)) +
                          __uint_as_float((unsigned)a1) +
                          __uint_as_float((unsigned)(a1 >> 32));
                o += __shfl_xor_sync(0xffffffffu, o, 16);   // combine f-halves
                if (h == 0) {
                    int orow = rowA + r * G;
                    out[(size_t)orow * DDIM + d] = (o > 0.f) ? o : 0.f;
                }
            }
        }

        rowA += 4 * G;
        p += 2;
    }
}

// ---------------------------------------------------------------------------
extern "C" void kernel_launch(void* const* d_in, const int* in_sizes, int n_in,
                              void* d_out, int out_size) {
    const float* x_self  = (const float*)d_in[0];   // [1024,32,128]
    const float* x_neigh = (const float*)d_in[1];   // [1024,32,25,128]
    const float* w_feat  = (const float*)d_in[2];   // [128,128]
    const float* a_self  = (const float*)d_in[3];   // [128,1]
    const float* a_neigh = (const float*)d_in[4];   // [128,1]
    float*       out     = (float*)d_out;           // [1024,32,128]

    fused_gat_kernel<<<GRIDSZ, THREADS>>>(x_self, x_neigh, w_feat,
                                          a_self, a_neigh, out);
}

// round 13
// speedup vs baseline: 1.1550x; 1.1550x over previous
#include <cuda_runtime.h>
#include <cstdint>
#include <math.h>

// Problem constants: B=1024, H=32, N=25, F=D=128
#define BH      32768
#define NK      26                  // softmax/aggregation length (self + 25)
#define FDIM    128
#define DDIM    128
#define GRIDSZ  304                 // 2 blocks/SM x 152 SMs (GB300)
#define THREADS 256
#define NPAIR   3                   // TMA ring depth in row-pairs
#define NSLOT   (2 * NPAIR)

#define ROW_FLOATS   (NK * FDIM)    // 3328 floats per staged row tile
#define SELF_BYTES   (FDIM * 4)     // 512
#define NEIGH_BYTES  (25 * FDIM * 4)// 12800
#define ROW_BYTES    (SELF_BYTES + NEIGH_BYTES) // 13312

typedef unsigned long long ull;

// ---------------------------------------------------------------------------
// TMA 1D bulk copy + mbarrier helpers
// ---------------------------------------------------------------------------
__device__ __forceinline__ void tma_bulk_1d(unsigned dst, const void* src,
                                            unsigned bytes, unsigned mbar) {
    asm volatile(
        "cp.async.bulk.shared::cluster.global.mbarrier::complete_tx::bytes "
        "[%0], [%1], %2, [%3];\n"
        :: "r"(dst), "l"(src), "r"(bytes), "r"(mbar) : "memory");
}
__device__ __forceinline__ void mbar_init(unsigned mbar, unsigned cnt) {
    asm volatile("mbarrier.init.shared.b64 [%0], %1;\n" :: "r"(mbar), "r"(cnt) : "memory");
}
__device__ __forceinline__ void mbar_expect_tx(unsigned mbar, unsigned bytes) {
    asm volatile("mbarrier.arrive.expect_tx.shared.b64 _, [%0], %1;\n"
                 :: "r"(mbar), "r"(bytes) : "memory");
}
__device__ __forceinline__ void mbar_wait(unsigned mbar, unsigned parity) {
    asm volatile(
        "{\n\t"
        ".reg .pred P;\n\t"
        "WL_%=:\n\t"
        "mbarrier.try_wait.parity.acquire.cta.shared::cta.b64 P, [%0], %1, 0x989680;\n\t"
        "@P bra WD_%=;\n\t"
        "bra WL_%=;\n\t"
        "WD_%=:\n\t"
        "}"
        :: "r"(mbar), "r"(parity) : "memory");
}

__global__ void __launch_bounds__(THREADS, 2)
fused_gat_kernel(const float* __restrict__ x_self,
                 const float* __restrict__ x_neigh,
                 const float* __restrict__ W,
                 const float* __restrict__ a_s,
                 const float* __restrict__ a_n,
                 float* __restrict__ out) {
    __shared__ __align__(128) float xs[NSLOT][ROW_FLOATS];      // ~80 KB ring
    __shared__ __align__(16)  float wa_s_sm[FDIM];
    __shared__ __align__(16)  float wa_n_sm[FDIM];
    __shared__ __align__(16)  float xpart[4][8][FDIM];           // per-(warp,group) partials
    __shared__ float zpart[4][4];                                // per-warp exp sums
    __shared__ __align__(16)  float xagg_il[4][FDIM];            // interleaved for GEMV
    __shared__ __align__(8)   ull  mbars[NPAIR];

    const int t    = threadIdx.x;
    const int warp = t >> 5;
    const int lane = t & 31;

    const unsigned xs_base   = (unsigned)__cvta_generic_to_shared(&xs[0][0]);
    const unsigned mbar_base = (unsigned)__cvta_generic_to_shared(&mbars[0]);

    if (t == 0) {
#pragma unroll
        for (int i = 0; i < NPAIR; i++) mbar_init(mbar_base + 8 * i, 1);
        asm volatile("fence.proxy.async.shared::cta;\n" ::: "memory");
    }
    __syncthreads();

    const int G = GRIDSZ;
    auto issue_pair = [&](int p) {
        int rA = blockIdx.x + 2 * p * G;
        if (rA >= BH) return;
        int rB = rA + G;
        int nrows = (rB < BH) ? 2 : 1;
        unsigned mb = mbar_base + 8 * (p % NPAIR);
        unsigned s0 = xs_base + (unsigned)(2 * (p % NPAIR)) * (ROW_FLOATS * 4);
        mbar_expect_tx(mb, (unsigned)ROW_BYTES * nrows);
        tma_bulk_1d(s0,              x_self  + (size_t)rA * FDIM,      SELF_BYTES,  mb);
        tma_bulk_1d(s0 + SELF_BYTES, x_neigh + (size_t)rA * 25 * FDIM, NEIGH_BYTES, mb);
        if (nrows == 2) {
            unsigned s1 = s0 + ROW_FLOATS * 4;
            tma_bulk_1d(s1,              x_self  + (size_t)rB * FDIM,      SELF_BYTES,  mb);
            tma_bulk_1d(s1 + SELF_BYTES, x_neigh + (size_t)rB * 25 * FDIM, NEIGH_BYTES, mb);
        }
    };
    if (t == 0) { issue_pair(0); issue_pair(1); issue_pair(2); }

    // ---------------- prologue: wa = W @ a  (2 threads per f) ----------------
    {
        const int f  = t >> 1, hf = t & 1;
        const float* wr = W + (size_t)f * DDIM + hf * 64;
        const float* as = a_s + hf * 64;
        const float* an = a_n + hf * 64;
        float vs = 0.f, vn = 0.f;
#pragma unroll
        for (int j = 0; j < 64; j++) {
            float w = wr[j];
            vs = fmaf(w, as[j], vs);
            vn = fmaf(w, an[j], vn);
        }
        vs += __shfl_xor_sync(0xffffffffu, vs, 1);
        vn += __shfl_xor_sync(0xffffffffu, vn, 1);
        if (!hf) { wa_s_sm[f] = vs; wa_n_sm[f] = vn; }
    }

    // W register cache, packed f32x2 along f (for GEMV).
    const int h = lane >> 4;
    const int d = warp * 16 + (lane & 15);
    ull Wreg2[32];
#pragma unroll
    for (int i = 0; i < 32; i++) {
        int f = h * 64 + 2 * i;
        unsigned lo = __float_as_uint(W[(size_t)f * DDIM + d]);
        unsigned hi = __float_as_uint(W[(size_t)(f + 1) * DDIM + d]);
        Wreg2[i] = ((ull)hi << 32) | lo;
    }
    __syncthreads();     // wa_* visible

    // ---- 16-lane-dot layout: group g16 owns a dot; lane covers chunks j0,j1 ----
    const int g16 = lane >> 4;          // dot group within warp (0/1)
    const int s16 = lane & 15;          // sublane within group
    const int j0  = s16 + 16 * g16;     // 16B-chunk index, instr 0
    const int j1  = s16 + 16 - 16 * g16;// 16B-chunk index, instr 1 (disjoint from j0)
    const float4 wj0 = reinterpret_cast<const float4*>(wa_n_sm)[j0];
    const float4 wj1 = reinterpret_cast<const float4*>(wa_n_sm)[j1];
    const float4 wasL = reinterpret_cast<const float4*>(wa_s_sm)[lane];

    const int rsel = warp >> 2;        // warps 0-3 -> rows {0,2}, 4-7 -> rows {1,3}
    const int w4   = warp & 3;

    // process one staged row: online softmax + e-weighted aggregation
    auto do_row = [&](const float* slot, int r) {
        // self score ss = row0 . wa_s (full-warp dot, natural mapping)
        float4 x0 = reinterpret_cast<const float4*>(slot)[lane];
        float ss;
        ss =      x0.x * wasL.x;  ss = fmaf(x0.y, wasL.y, ss);
        ss = fmaf(x0.z, wasL.z, ss); ss = fmaf(x0.w, wasL.w, ss);
        ss += __shfl_xor_sync(0xffffffffu, ss, 16);
        ss += __shfl_xor_sync(0xffffffffu, ss, 8);
        ss += __shfl_xor_sync(0xffffffffu, ss, 4);
        ss += __shfl_xor_sync(0xffffffffu, ss, 2);
        ss += __shfl_xor_sync(0xffffffffu, ss, 1);

        float4 paA = make_float4(0.f, 0.f, 0.f, 0.f);
        float4 paB = make_float4(0.f, 0.f, 0.f, 0.f);
        float  z = 0.f;
#pragma unroll
        for (int P = 0; P < 4; P++) {
            const int k  = w4 + 8 * P + 4 * g16;   // group's dot index
            const int kc = (k < NK) ? k : 0;       // clamp (result discarded)
            const float4* row4 = reinterpret_cast<const float4*>(slot + kc * FDIM);
            float4 xa = row4[j0];
            float4 xb = row4[j1];
            float v;
            v =      xa.x * wj0.x;  v = fmaf(xa.y, wj0.y, v);
            v = fmaf(xa.z, wj0.z, v); v = fmaf(xa.w, wj0.w, v);
            v = fmaf(xb.x, wj1.x, v); v = fmaf(xb.y, wj1.y, v);
            v = fmaf(xb.z, wj1.z, v); v = fmaf(xb.w, wj1.w, v);
            // reduce within the 16-lane group (full-warp shuffle participation)
            v += __shfl_xor_sync(0xffffffffu, v, 8);
            v += __shfl_xor_sync(0xffffffffu, v, 4);
            v += __shfl_xor_sync(0xffffffffu, v, 2);
            v += __shfl_xor_sync(0xffffffffu, v, 1);
            if (k < NK) {
                float uu = ss + v;
                uu = (uu > 0.f) ? uu : 0.2f * uu;   // LeakyReLU(0.2)
                float e = __expf(uu);
                paA.x = fmaf(e, xa.x, paA.x); paA.y = fmaf(e, xa.y, paA.y);
                paA.z = fmaf(e, xa.z, paA.z); paA.w = fmaf(e, xa.w, paA.w);
                paB.x = fmaf(e, xb.x, paB.x); paB.y = fmaf(e, xb.y, paB.y);
                paB.z = fmaf(e, xb.z, paB.z); paB.w = fmaf(e, xb.w, paB.w);
                z += e;
            }
        }
        z += __shfl_xor_sync(0xffffffffu, z, 16);   // combine groups (z group-uniform)
        float* xp = &xpart[r][2 * w4 + g16][0];
        *reinterpret_cast<float4*>(xp + 4 * j0) = paA;
        *reinterpret_cast<float4*>(xp + 4 * j1) = paB;
        if (lane == 0) zpart[r][w4] = z;
    };

    // ---------------- main loop: 4 rows (2 pairs) per iteration ----------------
    int rowA = blockIdx.x;
    int p = 0;

    while (rowA < BH) {
        const bool rv1 = rowA + G     < BH;
        const bool rv2 = rowA + 2 * G < BH;
        const bool rv3 = rowA + 3 * G < BH;

        mbar_wait(mbar_base + 8 * (p % NPAIR), (unsigned)((p / NPAIR) & 1));
        if (rv2)
            mbar_wait(mbar_base + 8 * ((p + 1) % NPAIR),
                      (unsigned)(((p + 1) / NPAIR) & 1));

        const float* slotU = &xs[2 * (p % NPAIR) + rsel][0];
        const float* slotV = &xs[2 * ((p + 1) % NPAIR) + rsel][0];
        const bool wu = (rsel == 0) || rv1;
        const bool wv = rv2 && ((rsel == 0) || rv3);

        if (wu) do_row(slotU, rsel);
        if (wv) do_row(slotV, rsel + 2);
        __syncthreads();               // B3: partials visible; tiles dead

        // refill the two consumed pairs
        if (t == 0) { issue_pair(p + 3); issue_pair(p + 4); }

        // ---- reduce 8 partials, divide by Z -> interleaved xagg ----
        {
            const int r  = t >> 6;     // row 0..3
            const int fp = t & 63;     // f-pair index
            const float* xp = &xpart[r][0][2 * fp];
            ull q0 = *reinterpret_cast<const ull*>(xp);
            ull q1 = *reinterpret_cast<const ull*>(xp + FDIM);
            ull q2 = *reinterpret_cast<const ull*>(xp + 2 * FDIM);
            ull q3 = *reinterpret_cast<const ull*>(xp + 3 * FDIM);
            ull q4 = *reinterpret_cast<const ull*>(xp + 4 * FDIM);
            ull q5 = *reinterpret_cast<const ull*>(xp + 5 * FDIM);
            ull q6 = *reinterpret_cast<const ull*>(xp + 6 * FDIM);
            ull q7 = *reinterpret_cast<const ull*>(xp + 7 * FDIM);
            asm volatile("add.rn.f32x2 %0, %0, %1;\n" : "+l"(q0) : "l"(q1));
            asm volatile("add.rn.f32x2 %0, %0, %1;\n" : "+l"(q2) : "l"(q3));
            asm volatile("add.rn.f32x2 %0, %0, %1;\n" : "+l"(q4) : "l"(q5));
            asm volatile("add.rn.f32x2 %0, %0, %1;\n" : "+l"(q6) : "l"(q7));
            asm volatile("add.rn.f32x2 %0, %0, %1;\n" : "+l"(q0) : "l"(q2));
            asm volatile("add.rn.f32x2 %0, %0, %1;\n" : "+l"(q4) : "l"(q6));
            asm volatile("add.rn.f32x2 %0, %0, %1;\n" : "+l"(q0) : "l"(q4));
            float rz = __fdividef(1.f, zpart[r][0] + zpart[r][1]
                                     + zpart[r][2] + zpart[r][3]);
            ull rz2;
            asm volatile("mov.b64 %0, {%1, %1};\n" : "=l"(rz2) : "f"(rz));
            asm volatile("mul.rn.f32x2 %0, %0, %1;\n" : "+l"(q0) : "l"(rz2));
            const int sOff = (fp < 32) ? (8 * (fp >> 1) + 2 * (fp & 1))
                                       : (8 * ((fp - 32) >> 1) + 4 + 2 * (fp & 1));
            *reinterpret_cast<ull*>(&xagg_il[r][sOff]) = q0;
        }
        __syncthreads();               // B4: xagg visible

        // ---- GEMV (4 rows) from packed register W; conflict-free LDS.128 ----
#pragma unroll
        for (int r = 0; r < 4; r++) {
            const bool rok = (r == 0) || (r == 1 && rv1) || (r == 2 && rv2) || (r == 3 && rv3);
            if (rok) {
                ull a0 = 0, a1 = 0;
#pragma unroll
                for (int i = 0; i < 16; i++) {
                    longlong2 q = *reinterpret_cast<const longlong2*>(
                        &xagg_il[r][8 * i + 4 * h]);
                    asm volatile("fma.rn.f32x2 %0, %1, %2, %0;\n"
                                 : "+l"(a0) : "l"((ull)q.x), "l"(Wreg2[2 * i]));
                    asm volatile("fma.rn.f32x2 %0, %1, %2, %0;\n"
                                 : "+l"(a1) : "l"((ull)q.y), "l"(Wreg2[2 * i + 1]));
                }
                float o = __uint_as_float((unsigned)a0) +
                          __uint_as_float((unsigned)(a0 >> 32)) +
                          __uint_as_float((unsigned)a1) +
                          __uint_as_float((unsigned)(a1 >> 32));
                o += __shfl_xor_sync(0xffffffffu, o, 16);   // combine f-halves
                if (h == 0) {
                    int orow = rowA + r * G;
                    out[(size_t)orow * DDIM + d] = (o > 0.f) ? o : 0.f;
                }
            }
        }

        rowA += 4 * G;
        p += 2;
    }
}

// ---------------------------------------------------------------------------
extern "C" void kernel_launch(void* const* d_in, const int* in_sizes, int n_in,
                              void* d_out, int out_size) {
    const float* x_self  = (const float*)d_in[0];   // [1024,32,128]
    const float* x_neigh = (const float*)d_in[1];   // [1024,32,25,128]
    const float* w_feat  = (const float*)d_in[2];   // [128,128]
    const float* a_self  = (const float*)d_in[3];   // [128,1]
    const float* a_neigh = (const float*)d_in[4];   // [128,1]
    float*       out     = (float*)d_out;           // [1024,32,128]

    fused_gat_kernel<<<GRIDSZ, THREADS>>>(x_self, x_neigh, w_feat,
                                          a_self, a_neigh, out);
}